// round 1
// baseline (speedup 1.0000x reference)
#include <cuda_runtime.h>
#include <cstdint>

// ---------------- problem constants ----------------
#define AN      3
#define NC      80
#define NCH     85          // C+5
#define HH      52
#define WW      52
#define HWSZ    (HH*WW)     // 2704
#define MAXB    16
#define MAXN    1024
#define CELLS   (MAXB*AN*HWSZ)   // 129792
#define ROWF4   13          // 52 floats / 4
#define VECS    (NCH*ROWF4) // 1105 float4 per (b,a,h) row-block
#define TILEF   (NCH*WW)    // 4420 floats

__constant__ float c_aw[AN] = {10.f, 16.f, 33.f};
__constant__ float c_ah[AN] = {13.f, 30.f, 23.f};

// ---------------- device scratch (no allocations allowed) ----------------
__device__ unsigned char g_mask[CELLS];
__device__ double g_noobj_sum;
__device__ int    g_noobj_cnt;
__device__ int    g_cell[MAXN];
__device__ float  g_tx[MAXN], g_ty[MAXN], g_tw[MAXN], g_th[MAXN];
__device__ int    g_lab[MAXN];

__device__ __forceinline__ float sigf(float z) { return 1.0f / (1.0f + expf(-z)); }

// ---------------- kernel 1: init mask + accumulators ----------------
__global__ void k_init(int total) {
    int i = blockIdx.x * blockDim.x + threadIdx.x;
    if (i < total) g_mask[i] = 1;
    if (i == 0) { g_noobj_sum = 0.0; g_noobj_cnt = 0; }
}

// ---------------- kernel 2: per-target scatter ----------------
__global__ void k_targets(const float* __restrict__ t, int N) {
    int n = threadIdx.x;
    if (n >= N) return;
    const float* tn = t + 6 * n;
    int   img = (int)tn[0];
    float gx = tn[1] * (float)WW;
    float gy = tn[2] * (float)HH;
    float gw = tn[3] * (float)WW;
    float gh = tn[4] * (float)HH;
    int   lab = (int)tn[5];

    float iou[AN];
    int best = 0;
    #pragma unroll
    for (int a = 0; a < AN; a++) {
        float aw = c_aw[a], ah = c_ah[a];
        float inter = fminf(aw, gw) * fminf(ah, gh);
        iou[a] = inter / (aw * ah + 1e-16f + gw * gh - inter);
    }
    if (iou[1] > iou[best]) best = 1;
    if (iou[2] > iou[best]) best = 2;

    int gi = (int)gx;
    int gj = (int)gy;
    int cell = ((img * AN + best) * HH + gj) * WW + gi;

    g_cell[n] = cell;
    g_tx[n]   = gx - floorf(gx);
    g_ty[n]   = gy - floorf(gy);
    g_tw[n]   = logf(gw / c_aw[best] + 1e-16f);
    g_th[n]   = logf(gh / c_ah[best] + 1e-16f);
    g_lab[n]  = lab;

    // obj cell zeroes noobj mask
    g_mask[cell] = 0;
    // ignore: any anchor with IoU > 0.5 at (img, a, gj, gi)
    #pragma unroll
    for (int a = 0; a < AN; a++)
        if (iou[a] > 0.5f)
            g_mask[((img * AN + a) * HH + gj) * WW + gi] = 0;
}

// ---------------- kernel 3: transform + transpose + noobj reduce ----------------
__global__ __launch_bounds__(256) void k_main(const float* __restrict__ x,
                                              float* __restrict__ out) {
    __shared__ float tile[TILEF];
    __shared__ float s_sum;
    __shared__ int   s_cnt;

    int bx = blockIdx.x;
    int h = bx % HH;
    int a = (bx / HH) % AN;
    int b = bx / (HH * AN);

    if (threadIdx.x == 0) { s_sum = 0.0f; s_cnt = 0; }
    __syncthreads();

    const float* xb = x + ((size_t)(b * (AN * NCH) + a * NCH)) * HWSZ + h * WW;
    const float aw = c_aw[a], ah = c_ah[a];
    const float hf = (float)h;
    const int cellbase = ((b * AN + a) * HH + h) * WW;

    float lsum = 0.0f;
    int   lcnt = 0;

    for (int idx = threadIdx.x; idx < VECS; idx += blockDim.x) {
        int c  = idx / ROWF4;
        int wv = idx - c * ROWF4;
        float4 v = *reinterpret_cast<const float4*>(xb + (size_t)c * HWSZ + wv * 4);
        float r[4] = {v.x, v.y, v.z, v.w};
        int w0 = wv * 4;
        #pragma unroll
        for (int j = 0; j < 4; j++) {
            float z = r[j];
            float val;
            int w = w0 + j;
            if (c == 0)      val = (sigf(z) + (float)w) * 8.0f;
            else if (c == 1) val = (sigf(z) + hf) * 8.0f;
            else if (c == 2) val = expf(z) * aw;
            else if (c == 3) val = expf(z) * ah;
            else {
                val = sigf(z);
                if (c == 4 && g_mask[cellbase + w]) {
                    lsum -= logf(1.0f - val);   // t=0 branch of BCE
                    lcnt++;
                }
            }
            tile[w * NCH + c] = val;
        }
    }
    if (lcnt) { atomicAdd(&s_sum, lsum); atomicAdd(&s_cnt, lcnt); }
    __syncthreads();
    if (threadIdx.x == 0) {
        atomicAdd(&g_noobj_sum, (double)s_sum);
        atomicAdd(&g_noobj_cnt, s_cnt);
    }
    // contiguous write: 4420 floats = 1105 float4, 16B-aligned (pos0*85*4 % 16 == 0)
    size_t pos0 = (size_t)b * (AN * HWSZ) + (size_t)a * HWSZ + (size_t)h * WW;
    float4* o = reinterpret_cast<float4*>(out + pos0 * NCH);
    const float4* ts = reinterpret_cast<const float4*>(tile);
    for (int i = threadIdx.x; i < VECS; i += blockDim.x) o[i] = ts[i];
}

// ---------------- kernel 4: obj-cell losses + final combine ----------------
__global__ void k_obj(const float* __restrict__ x, float* __restrict__ out,
                      int N, int out_size) {
    __shared__ int   sc[MAXN];
    __shared__ float s_sx, s_sy, s_sw, s_sh, s_conf, s_cls;
    __shared__ int   s_nobj;

    int n = threadIdx.x;
    if (n == 0) { s_sx = s_sy = s_sw = s_sh = s_conf = s_cls = 0.0f; s_nobj = 0; }
    if (n < N) sc[n] = g_cell[n];
    __syncthreads();

    if (n < N) {
        // last-write-wins dedupe: winner is the highest target index per cell
        bool win = true;
        for (int m = n + 1; m < N; m++)
            if (sc[m] == sc[n]) { win = false; break; }
        if (win) {
            int cell = sc[n];
            int i = cell % WW;
            int j = (cell / WW) % HH;
            int a = (cell / HWSZ) % AN;
            int b = cell / (AN * HWSZ);
            const float* xb = x + ((size_t)(b * (AN * NCH) + a * NCH)) * HWSZ
                                + (size_t)j * WW + i;
            float z0 = xb[0];
            float z2 = xb[(size_t)2 * HWSZ];
            float z4 = xb[(size_t)4 * HWSZ];
            float cx = sigf(z0);
            float dx = cx - g_tx[n];
            float dy = cx - g_ty[n];          // reference bug: y-loss uses cx
            float dw = z2 - g_tw[n];
            float dh = z2 - g_th[n];          // reference bug: h-loss uses pw
            float p4 = fmaxf(sigf(z4), 1e-12f);
            float conf = -logf(p4);           // t=1 at obj cell
            int lab = g_lab[n];
            float cls = 0.0f;
            for (int c = 0; c < NC; c++) {
                float p = fmaxf(sigf(xb[(size_t)(5 + c) * HWSZ]), 1e-12f);
                cls += (c == lab) ? -logf(p) : -logf(1.0f - p);
            }
            atomicAdd(&s_sx, dx * dx);
            atomicAdd(&s_sy, dy * dy);
            atomicAdd(&s_sw, dw * dw);
            atomicAdd(&s_sh, dh * dh);
            atomicAdd(&s_conf, conf);
            atomicAdd(&s_cls, cls);
            atomicAdd(&s_nobj, 1);
        }
    }
    __syncthreads();
    if (n == 0) {
        float nobj = fmaxf((float)s_nobj, 1.0f);
        float nno  = fmaxf((float)g_noobj_cnt, 1.0f);
        float total = (s_sx + s_sy + s_sw + s_sh) / nobj
                    + 1.0f * (s_conf / nobj)
                    + 0.5f * (float)(g_noobj_sum / (double)nno)
                    + s_cls / (nobj * (float)NC);
        out[out_size - 1] = total;
    }
}

// ---------------- launcher ----------------
extern "C" void kernel_launch(void* const* d_in, const int* in_sizes, int n_in,
                              void* d_out, int out_size) {
    const float* x   = (const float*)d_in[0];
    const float* tgt = (const float*)d_in[1];
    float* out = (float*)d_out;

    int B = in_sizes[0] / (AN * NCH * HWSZ);   // 16
    int N = in_sizes[1] / 6;                   // 256
    int total_cells = B * AN * HWSZ;

    k_init<<<(total_cells + 255) / 256, 256>>>(total_cells);
    int tN = ((N + 31) / 32) * 32;
    k_targets<<<1, tN>>>(tgt, N);
    k_main<<<B * AN * HH, 256>>>(x, out);
    k_obj<<<1, tN>>>(x, out, N, out_size);
}

// round 2
// speedup vs baseline: 1.1000x; 1.1000x over previous
#include <cuda_runtime.h>
#include <cstdint>

// ---------------- problem constants ----------------
#define AN      3
#define NC      80
#define NCH     85          // C+5
#define HH      52
#define WW      52
#define HWSZ    (HH*WW)     // 2704
#define MAXB    16
#define MAXN    1024
#define CELLS   (MAXB*AN*HWSZ)   // 129792
#define ROWF4   13          // 52 floats / 4
#define VECS    (NCH*ROWF4) // 1105 float4 per (b,a,h) row-block
#define TILEF   (NCH*WW)    // 4420 floats

__constant__ float c_aw[AN] = {10.f, 16.f, 33.f};
__constant__ float c_ah[AN] = {13.f, 30.f, 23.f};

// ---------------- device scratch (no allocations allowed) ----------------
__device__ unsigned char g_mask[CELLS];
__device__ double g_noobj_sum;
__device__ int    g_noobj_cnt;
__device__ int    g_cell[MAXN];
__device__ float  g_tx[MAXN], g_ty[MAXN], g_tw[MAXN], g_th[MAXN];
__device__ int    g_lab[MAXN];

// ---- fast math helpers (explicit approx instructions, flag-independent) ----
#define L2E 1.4426950408889634f

__device__ __forceinline__ float fex2(float x) {
    float r; asm("ex2.approx.ftz.f32 %0, %1;" : "=f"(r) : "f"(x)); return r;
}
__device__ __forceinline__ float frcp(float x) {
    float r; asm("rcp.approx.ftz.f32 %0, %1;" : "=f"(r) : "f"(x)); return r;
}
__device__ __forceinline__ float flg2(float x) {
    float r; asm("lg2.approx.ftz.f32 %0, %1;" : "=f"(r) : "f"(x)); return r;
}
// sigmoid: 1/(1+2^(-z*log2e)) -> FMUL + EX2 + FADD + RCP  (2 MUFU, 2 ALU)
__device__ __forceinline__ float fsig(float z) {
    return frcp(1.0f + fex2(-L2E * z));
}
__device__ __forceinline__ float fexp(float z) { return fex2(L2E * z); }
// accurate-enough sigmoid for loss path (same approx; err ~3e-7)
__device__ __forceinline__ float sigf(float z) { return fsig(z); }

// ---------------- kernel 1: init mask + accumulators ----------------
__global__ void k_init(int total) {
    int i = blockIdx.x * blockDim.x + threadIdx.x;
    if (i < total) g_mask[i] = 1;
    if (i == 0) { g_noobj_sum = 0.0; g_noobj_cnt = 0; }
}

// ---------------- kernel 2: per-target scatter ----------------
__global__ void k_targets(const float* __restrict__ t, int N) {
    int n = threadIdx.x;
    if (n >= N) return;
    const float* tn = t + 6 * n;
    int   img = (int)tn[0];
    float gx = tn[1] * (float)WW;
    float gy = tn[2] * (float)HH;
    float gw = tn[3] * (float)WW;
    float gh = tn[4] * (float)HH;
    int   lab = (int)tn[5];

    float iou[AN];
    int best = 0;
    #pragma unroll
    for (int a = 0; a < AN; a++) {
        float aw = c_aw[a], ah = c_ah[a];
        float inter = fminf(aw, gw) * fminf(ah, gh);
        iou[a] = inter / (aw * ah + 1e-16f + gw * gh - inter);
    }
    if (iou[1] > iou[best]) best = 1;
    if (iou[2] > iou[best]) best = 2;

    int gi = (int)gx;
    int gj = (int)gy;
    int cell = ((img * AN + best) * HH + gj) * WW + gi;

    g_cell[n] = cell;
    g_tx[n]   = gx - floorf(gx);
    g_ty[n]   = gy - floorf(gy);
    g_tw[n]   = logf(gw / c_aw[best] + 1e-16f);
    g_th[n]   = logf(gh / c_ah[best] + 1e-16f);
    g_lab[n]  = lab;

    g_mask[cell] = 0;
    #pragma unroll
    for (int a = 0; a < AN; a++)
        if (iou[a] > 0.5f)
            g_mask[((img * AN + a) * HH + gj) * WW + gi] = 0;
}

// ---------------- kernel 3: transform + transpose + noobj reduce ----------------
__global__ __launch_bounds__(256) void k_main(const float* __restrict__ x,
                                              float* __restrict__ out) {
    __shared__ float tile[TILEF];
    __shared__ float s_sum;
    __shared__ int   s_cnt;

    int bx = blockIdx.x;
    int h = bx % HH;
    int a = (bx / HH) % AN;
    int b = bx / (HH * AN);

    if (threadIdx.x == 0) { s_sum = 0.0f; s_cnt = 0; }
    __syncthreads();

    const float* xb = x + ((size_t)(b * (AN * NCH) + a * NCH)) * HWSZ + h * WW;
    const float aw = c_aw[a], ah = c_ah[a];
    const float hf = (float)h;
    const int cellbase = ((b * AN + a) * HH + h) * WW;

    float lsum = 0.0f;
    int   lcnt = 0;

    for (int idx = threadIdx.x; idx < VECS; idx += blockDim.x) {
        int c  = idx / ROWF4;              // constant div -> umulhi, cheap
        int wv = idx - c * ROWF4;
        float4 v = *reinterpret_cast<const float4*>(xb + (size_t)c * HWSZ + wv * 4);
        float r[4] = {v.x, v.y, v.z, v.w};
        int w0 = wv * 4;
        if (c == 0) {
            #pragma unroll
            for (int j = 0; j < 4; j++)
                tile[(w0 + j) * NCH] = (fsig(r[j]) + (float)(w0 + j)) * 8.0f;
        } else if (c == 1) {
            #pragma unroll
            for (int j = 0; j < 4; j++)
                tile[(w0 + j) * NCH + 1] = (fsig(r[j]) + hf) * 8.0f;
        } else if (c == 2) {
            #pragma unroll
            for (int j = 0; j < 4; j++)
                tile[(w0 + j) * NCH + 2] = fexp(r[j]) * aw;
        } else if (c == 3) {
            #pragma unroll
            for (int j = 0; j < 4; j++)
                tile[(w0 + j) * NCH + 3] = fexp(r[j]) * ah;
        } else if (c == 4) {
            #pragma unroll
            for (int j = 0; j < 4; j++) {
                float val = fsig(r[j]);
                int w = w0 + j;
                if (g_mask[cellbase + w]) {
                    // -log(1-p) = -lg2(1-p)/lg2(e)
                    lsum -= flg2(1.0f - val) * 0.6931471805599453f;
                    lcnt++;
                }
                tile[w * NCH + 4] = val;
            }
        } else {
            #pragma unroll
            for (int j = 0; j < 4; j++)
                tile[(w0 + j) * NCH + c] = fsig(r[j]);
        }
    }
    if (lcnt) { atomicAdd(&s_sum, lsum); atomicAdd(&s_cnt, lcnt); }
    __syncthreads();
    if (threadIdx.x == 0) {
        atomicAdd(&g_noobj_sum, (double)s_sum);
        atomicAdd(&g_noobj_cnt, s_cnt);
    }
    // contiguous write: 4420 floats = 1105 float4
    size_t pos0 = (size_t)b * (AN * HWSZ) + (size_t)a * HWSZ + (size_t)h * WW;
    float4* o = reinterpret_cast<float4*>(out + pos0 * NCH);
    const float4* ts = reinterpret_cast<const float4*>(tile);
    #pragma unroll 2
    for (int i = threadIdx.x; i < VECS; i += blockDim.x) o[i] = ts[i];
}

// ---------------- kernel 4: obj-cell losses + final combine ----------------
__global__ void k_obj(const float* __restrict__ x, float* __restrict__ out,
                      int N, int out_size) {
    __shared__ int   sc[MAXN];
    __shared__ float s_sx, s_sy, s_sw, s_sh, s_conf, s_cls;
    __shared__ int   s_nobj;

    int n = threadIdx.x;
    if (n == 0) { s_sx = s_sy = s_sw = s_sh = s_conf = s_cls = 0.0f; s_nobj = 0; }
    if (n < N) sc[n] = g_cell[n];
    __syncthreads();

    if (n < N) {
        // last-write-wins dedupe: winner is the highest target index per cell
        bool win = true;
        for (int m = n + 1; m < N; m++)
            if (sc[m] == sc[n]) { win = false; break; }
        if (win) {
            int cell = sc[n];
            int i = cell % WW;
            int j = (cell / WW) % HH;
            int a = (cell / HWSZ) % AN;
            int b = cell / (AN * HWSZ);
            const float* xb = x + ((size_t)(b * (AN * NCH) + a * NCH)) * HWSZ
                                + (size_t)j * WW + i;
            float z0 = xb[0];
            float z2 = xb[(size_t)2 * HWSZ];
            float z4 = xb[(size_t)4 * HWSZ];
            float cx = sigf(z0);
            float dx = cx - g_tx[n];
            float dy = cx - g_ty[n];          // reference bug: y-loss uses cx
            float dw = z2 - g_tw[n];
            float dh = z2 - g_th[n];          // reference bug: h-loss uses pw
            float p4 = fmaxf(sigf(z4), 1e-12f);
            float conf = -logf(p4);           // t=1 at obj cell
            int lab = g_lab[n];
            float cls = 0.0f;
            for (int c = 0; c < NC; c++) {
                float p = fmaxf(sigf(xb[(size_t)(5 + c) * HWSZ]), 1e-12f);
                cls += (c == lab) ? -logf(p) : -logf(1.0f - p);
            }
            atomicAdd(&s_sx, dx * dx);
            atomicAdd(&s_sy, dy * dy);
            atomicAdd(&s_sw, dw * dw);
            atomicAdd(&s_sh, dh * dh);
            atomicAdd(&s_conf, conf);
            atomicAdd(&s_cls, cls);
            atomicAdd(&s_nobj, 1);
        }
    }
    __syncthreads();
    if (n == 0) {
        float nobj = fmaxf((float)s_nobj, 1.0f);
        float nno  = fmaxf((float)g_noobj_cnt, 1.0f);
        float total = (s_sx + s_sy + s_sw + s_sh) / nobj
                    + 1.0f * (s_conf / nobj)
                    + 0.5f * (float)(g_noobj_sum / (double)nno)
                    + s_cls / (nobj * (float)NC);
        out[out_size - 1] = total;
    }
}

// ---------------- launcher ----------------
extern "C" void kernel_launch(void* const* d_in, const int* in_sizes, int n_in,
                              void* d_out, int out_size) {
    const float* x   = (const float*)d_in[0];
    const float* tgt = (const float*)d_in[1];
    float* out = (float*)d_out;

    int B = in_sizes[0] / (AN * NCH * HWSZ);   // 16
    int N = in_sizes[1] / 6;                   // 256
    int total_cells = B * AN * HWSZ;

    k_init<<<(total_cells + 255) / 256, 256>>>(total_cells);
    int tN = ((N + 31) / 32) * 32;
    k_targets<<<1, tN>>>(tgt, N);
    k_main<<<B * AN * HH, 256>>>(x, out);
    k_obj<<<1, tN>>>(x, out, N, out_size);
}

// round 3
// speedup vs baseline: 4.0813x; 3.7102x over previous
#include <cuda_runtime.h>
#include <cstdint>

// ---------------- problem constants ----------------
#define AN      3
#define NC      80
#define NCH     85          // C+5
#define HH      52
#define WW      52
#define HWSZ    (HH*WW)     // 2704
#define MAXN    1024
#define ROWF4   13          // 52 floats / 4
#define VECS    (NCH*ROWF4) // 1105 float4 per (b,a,h) row-block
#define TILEF   (NCH*WW)    // 4420 floats
#define TMAIN   512

__constant__ float c_aw[AN] = {10.f, 16.f, 33.f};
__constant__ float c_ah[AN] = {13.f, 30.f, 23.f};

// ---------------- device scratch (no allocations allowed) ----------------
#define CELLS   (16*AN*HWSZ)
__device__ unsigned char g_mask[CELLS];
__device__ double g_noobj_sum;
__device__ int    g_noobj_cnt;
__device__ unsigned int g_done;
__device__ int    g_cell[MAXN];
__device__ float  g_tx[MAXN], g_ty[MAXN], g_tw[MAXN], g_th[MAXN];
__device__ int    g_lab[MAXN];

// ---- fast math helpers ----
#define L2E 1.4426950408889634f
#define LN2 0.6931471805599453f

__device__ __forceinline__ float fex2(float x) {
    float r; asm("ex2.approx.ftz.f32 %0, %1;" : "=f"(r) : "f"(x)); return r;
}
__device__ __forceinline__ float frcp(float x) {
    float r; asm("rcp.approx.ftz.f32 %0, %1;" : "=f"(r) : "f"(x)); return r;
}
__device__ __forceinline__ float flg2(float x) {
    float r; asm("lg2.approx.ftz.f32 %0, %1;" : "=f"(r) : "f"(x)); return r;
}
__device__ __forceinline__ float fsig(float z) { return frcp(1.0f + fex2(-L2E * z)); }
__device__ __forceinline__ float fexp(float z) { return fex2(L2E * z); }

// ---------------- kernel 1: setup (mask init + accumulators + targets) ----------------
__global__ __launch_bounds__(256) void k_setup(const float* __restrict__ t, int N) {
    int n = threadIdx.x;
    // init accumulators
    if (n == 0) { g_noobj_sum = 0.0; g_noobj_cnt = 0; g_done = 0u; }
    // init mask to 1 (as 32-bit words)
    uint32_t* mw = reinterpret_cast<uint32_t*>(g_mask);
    #pragma unroll 4
    for (int i = n; i < CELLS / 4; i += 256) mw[i] = 0x01010101u;
    __syncthreads();

    if (n >= N) return;
    const float* tn = t + 6 * n;
    int   img = (int)tn[0];
    float gx = tn[1] * (float)WW;
    float gy = tn[2] * (float)HH;
    float gw = tn[3] * (float)WW;
    float gh = tn[4] * (float)HH;
    int   lab = (int)tn[5];

    float iou[AN];
    int best = 0;
    #pragma unroll
    for (int a = 0; a < AN; a++) {
        float aw = c_aw[a], ah = c_ah[a];
        float inter = fminf(aw, gw) * fminf(ah, gh);
        iou[a] = inter / (aw * ah + 1e-16f + gw * gh - inter);
    }
    if (iou[1] > iou[best]) best = 1;
    if (iou[2] > iou[best]) best = 2;

    int gi = (int)gx;
    int gj = (int)gy;
    int cell = ((img * AN + best) * HH + gj) * WW + gi;

    g_cell[n] = cell;
    g_tx[n]   = gx - floorf(gx);
    g_ty[n]   = gy - floorf(gy);
    g_tw[n]   = logf(gw / c_aw[best] + 1e-16f);
    g_th[n]   = logf(gh / c_ah[best] + 1e-16f);
    g_lab[n]  = lab;

    g_mask[cell] = 0;
    #pragma unroll
    for (int a = 0; a < AN; a++)
        if (iou[a] > 0.5f)
            g_mask[((img * AN + a) * HH + gj) * WW + gi] = 0;
}

// ---------------- kernel 2: transform + transpose + noobj reduce + finalize ----------------
__global__ __launch_bounds__(TMAIN) void k_main(const float* __restrict__ x,
                                                float* __restrict__ out,
                                                int N, int out_size) {
    __shared__ float tile[TILEF];
    __shared__ float s_sum;
    __shared__ int   s_cnt;
    __shared__ int   s_last;

    const int tid = threadIdx.x;
    const int bx = blockIdx.x;
    const int h = bx % HH;
    const int a = (bx / HH) % AN;
    const int b = bx / (HH * AN);

    if (tid == 0) { s_sum = 0.0f; s_cnt = 0; }
    __syncthreads();

    const float* __restrict__ xb =
        x + ((size_t)(b * (AN * NCH) + a * NCH)) * HWSZ + h * WW;
    const float aw = c_aw[a], ah = c_ah[a];
    const float hf = (float)h;
    const int cellbase = ((b * AN + a) * HH + h) * WW;

    float lsum = 0.0f;
    int   lcnt = 0;

    // VECS=1105, stride 512 (compile-time) -> 3 unrollable iterations
    #pragma unroll 3
    for (int idx = tid; idx < VECS; idx += TMAIN) {
        int c  = idx / ROWF4;
        int wv = idx - c * ROWF4;
        float4 v = *reinterpret_cast<const float4*>(xb + (size_t)c * HWSZ + wv * 4);
        float r[4] = {v.x, v.y, v.z, v.w};
        int w0 = wv * 4;
        if (c >= 5) {
            #pragma unroll
            for (int j = 0; j < 4; j++)
                tile[(w0 + j) * NCH + c] = fsig(r[j]);
        } else if (c == 0) {
            #pragma unroll
            for (int j = 0; j < 4; j++)
                tile[(w0 + j) * NCH] = (fsig(r[j]) + (float)(w0 + j)) * 8.0f;
        } else if (c == 1) {
            #pragma unroll
            for (int j = 0; j < 4; j++)
                tile[(w0 + j) * NCH + 1] = (fsig(r[j]) + hf) * 8.0f;
        } else if (c == 2) {
            #pragma unroll
            for (int j = 0; j < 4; j++)
                tile[(w0 + j) * NCH + 2] = fexp(r[j]) * aw;
        } else if (c == 3) {
            #pragma unroll
            for (int j = 0; j < 4; j++)
                tile[(w0 + j) * NCH + 3] = fexp(r[j]) * ah;
        } else { // c == 4
            #pragma unroll
            for (int j = 0; j < 4; j++) {
                float val = fsig(r[j]);
                int w = w0 + j;
                if (g_mask[cellbase + w]) {
                    lsum -= flg2(1.0f - val) * LN2;   // BCE t=0 branch
                    lcnt++;
                }
                tile[w * NCH + 4] = val;
            }
        }
    }
    // warp-level reduce, then one shared atomic per warp
    #pragma unroll
    for (int off = 16; off; off >>= 1) {
        lsum += __shfl_down_sync(0xffffffffu, lsum, off);
        lcnt += __shfl_down_sync(0xffffffffu, lcnt, off);
    }
    if ((tid & 31) == 0 && lcnt) { atomicAdd(&s_sum, lsum); atomicAdd(&s_cnt, lcnt); }
    __syncthreads();
    if (tid == 0 && s_cnt) {
        atomicAdd(&g_noobj_sum, (double)s_sum);
        atomicAdd(&g_noobj_cnt, s_cnt);
    }

    // contiguous write: 4420 floats = 1105 float4
    size_t pos0 = (size_t)b * (AN * HWSZ) + (size_t)a * HWSZ + (size_t)h * WW;
    float4* o = reinterpret_cast<float4*>(out + pos0 * NCH);
    const float4* ts = reinterpret_cast<const float4*>(tile);
    #pragma unroll 3
    for (int i = tid; i < VECS; i += TMAIN) o[i] = ts[i];

    // ---------------- last-block finalize ----------------
    __threadfence();
    __syncthreads();                 // all tile reads done; safe to reuse smem
    if (tid == 0)
        s_last = (atomicAdd(&g_done, 1u) == (unsigned)(gridDim.x - 1));
    __syncthreads();
    if (!s_last) return;

    int* sc = reinterpret_cast<int*>(tile);          // reuse smem
    float* acc = tile + MAXN;                        // 6 floats
    int* nobjp = reinterpret_cast<int*>(tile + MAXN + 8);
    if (tid == 0) {
        acc[0] = acc[1] = acc[2] = acc[3] = acc[4] = acc[5] = 0.0f;
        *nobjp = 0;
    }
    if (tid < N) sc[tid] = g_cell[tid];
    __syncthreads();

    if (tid < N) {
        // last-write-wins dedupe
        bool win = true;
        for (int m = tid + 1; m < N; m++)
            if (sc[m] == sc[tid]) { win = false; break; }
        if (win) {
            int cell = sc[tid];
            int i = cell % WW;
            int j = (cell / WW) % HH;
            int aa = (cell / HWSZ) % AN;
            int bb = cell / (AN * HWSZ);
            const float* xb2 = x + ((size_t)(bb * (AN * NCH) + aa * NCH)) * HWSZ
                                 + (size_t)j * WW + i;
            float z0 = xb2[0];
            float z2 = xb2[(size_t)2 * HWSZ];
            float z4 = xb2[(size_t)4 * HWSZ];
            float cx = fsig(z0);
            float dx = cx - g_tx[tid];
            float dy = cx - g_ty[tid];        // reference bug: y-loss uses cx
            float dw = z2 - g_tw[tid];
            float dh = z2 - g_th[tid];        // reference bug: h-loss uses pw
            float p4 = fmaxf(fsig(z4), 1e-12f);
            float conf = -flg2(p4) * LN2;     // t=1 at obj cell
            int lab = g_lab[tid];
            float cls = 0.0f;
            for (int c = 0; c < NC; c++) {
                float p = fmaxf(fsig(xb2[(size_t)(5 + c) * HWSZ]), 1e-12f);
                cls -= (c == lab) ? flg2(p) * LN2 : flg2(1.0f - p) * LN2;
            }
            atomicAdd(&acc[0], dx * dx);
            atomicAdd(&acc[1], dy * dy);
            atomicAdd(&acc[2], dw * dw);
            atomicAdd(&acc[3], dh * dh);
            atomicAdd(&acc[4], conf);
            atomicAdd(&acc[5], cls);
            atomicAdd(nobjp, 1);
        }
    }
    __syncthreads();
    if (tid == 0) {
        double nsum = atomicAdd(&g_noobj_sum, 0.0);      // ordered read
        int    ncnt = atomicAdd(&g_noobj_cnt, 0);
        float nobj = fmaxf((float)*nobjp, 1.0f);
        float nno  = fmaxf((float)ncnt, 1.0f);
        float total = (acc[0] + acc[1] + acc[2] + acc[3]) / nobj
                    + 1.0f * (acc[4] / nobj)
                    + 0.5f * (float)(nsum / (double)nno)
                    + acc[5] / (nobj * (float)NC);
        out[out_size - 1] = total;
    }
}

// ---------------- launcher ----------------
extern "C" void kernel_launch(void* const* d_in, const int* in_sizes, int n_in,
                              void* d_out, int out_size) {
    const float* x   = (const float*)d_in[0];
    const float* tgt = (const float*)d_in[1];
    float* out = (float*)d_out;

    int B = in_sizes[0] / (AN * NCH * HWSZ);   // 16
    int N = in_sizes[1] / 6;                   // 256

    k_setup<<<1, 256>>>(tgt, N);
    k_main<<<B * AN * HH, TMAIN>>>(x, out, N, out_size);
}

// round 4
// speedup vs baseline: 4.2696x; 1.0461x over previous
#include <cuda_runtime.h>
#include <cstdint>

// ---------------- problem constants ----------------
#define AN      3
#define NC      80
#define NCH     85          // C+5
#define HH      52
#define WW      52
#define HWSZ    (HH*WW)     // 2704
#define MAXN    1024
#define ROWF4   13          // 52 floats / 4
#define VECS    (NCH*ROWF4) // 1105 float4 per (b,a,h) row
#define TILEF   (NCH*WW)    // 4420 floats per row
#define TMAIN   512
#define MAXBLK  2048

__constant__ float c_aw[AN] = {10.f, 16.f, 33.f};
__constant__ float c_ah[AN] = {13.f, 30.f, 23.f};

// ---------------- device scratch (no allocations allowed) ----------------
#define CELLS   (16*AN*HWSZ)
__device__ unsigned char g_mask[CELLS];
__device__ float  g_psum[MAXBLK];
__device__ int    g_pcnt[MAXBLK];
__device__ int    g_cell[MAXN];
__device__ float  g_tx[MAXN], g_ty[MAXN], g_tw[MAXN], g_th[MAXN];
__device__ int    g_lab[MAXN];

// ---- fast math helpers ----
#define L2E 1.4426950408889634f
#define LN2 0.6931471805599453f

__device__ __forceinline__ float fex2(float x) {
    float r; asm("ex2.approx.ftz.f32 %0, %1;" : "=f"(r) : "f"(x)); return r;
}
__device__ __forceinline__ float frcp(float x) {
    float r; asm("rcp.approx.ftz.f32 %0, %1;" : "=f"(r) : "f"(x)); return r;
}
__device__ __forceinline__ float flg2(float x) {
    float r; asm("lg2.approx.ftz.f32 %0, %1;" : "=f"(r) : "f"(x)); return r;
}
__device__ __forceinline__ float fsig(float z) { return frcp(1.0f + fex2(-L2E * z)); }
__device__ __forceinline__ float fexp(float z) { return fex2(L2E * z); }

// ---------------- kernel 1: setup (mask init + targets) ----------------
__global__ __launch_bounds__(256) void k_setup(const float* __restrict__ t, int N) {
    int n = threadIdx.x;
    uint32_t* mw = reinterpret_cast<uint32_t*>(g_mask);
    #pragma unroll 4
    for (int i = n; i < CELLS / 4; i += 256) mw[i] = 0x01010101u;
    __syncthreads();

    if (n >= N) return;
    const float* tn = t + 6 * n;
    int   img = (int)tn[0];
    float gx = tn[1] * (float)WW;
    float gy = tn[2] * (float)HH;
    float gw = tn[3] * (float)WW;
    float gh = tn[4] * (float)HH;
    int   lab = (int)tn[5];

    float iou[AN];
    int best = 0;
    #pragma unroll
    for (int a = 0; a < AN; a++) {
        float aw = c_aw[a], ah = c_ah[a];
        float inter = fminf(aw, gw) * fminf(ah, gh);
        iou[a] = inter / (aw * ah + 1e-16f + gw * gh - inter);
    }
    if (iou[1] > iou[best]) best = 1;
    if (iou[2] > iou[best]) best = 2;

    int gi = (int)gx;
    int gj = (int)gy;
    int cell = ((img * AN + best) * HH + gj) * WW + gi;

    g_cell[n] = cell;
    g_tx[n]   = gx - floorf(gx);
    g_ty[n]   = gy - floorf(gy);
    g_tw[n]   = logf(gw / c_aw[best] + 1e-16f);
    g_th[n]   = logf(gh / c_ah[best] + 1e-16f);
    g_lab[n]  = lab;

    g_mask[cell] = 0;
    #pragma unroll
    for (int a = 0; a < AN; a++)
        if (iou[a] > 0.5f)
            g_mask[((img * AN + a) * HH + gj) * WW + gi] = 0;
}

// ---------------- kernel 2: transform + transpose (2 rows/block, no atomics) ----------------
__global__ __launch_bounds__(TMAIN) void k_main(const float* __restrict__ x,
                                                float* __restrict__ out) {
    __shared__ float tile[2 * TILEF];          // 35360 B
    __shared__ float s_wsum[16];
    __shared__ int   s_wcnt[16];

    const int tid = threadIdx.x;
    const int bx = blockIdx.x;
    const int hp = bx % (HH / 2);              // row-pair index
    const int a  = (bx / (HH / 2)) % AN;
    const int b  = bx / ((HH / 2) * AN);
    const int h0 = hp * 2;

    const float aw = c_aw[a], ah = c_ah[a];
    const float* __restrict__ plane = x + ((size_t)(b * AN + a) * NCH) * HWSZ;

    float lsum = 0.0f;
    int   lcnt = 0;

    #pragma unroll
    for (int rr = 0; rr < 2; rr++) {
        const int h = h0 + rr;
        const float hf = (float)h;
        const float* __restrict__ xb = plane + h * WW;
        const int cellbase = ((b * AN + a) * HH + h) * WW;
        float* __restrict__ trow = tile + rr * TILEF;

        #pragma unroll 3
        for (int idx = tid; idx < VECS; idx += TMAIN) {
            int c  = idx / ROWF4;
            int wv = idx - c * ROWF4;
            float4 v = *reinterpret_cast<const float4*>(xb + (size_t)c * HWSZ + wv * 4);
            float r[4] = {v.x, v.y, v.z, v.w};
            int w0 = wv * 4;
            if (c >= 5) {
                #pragma unroll
                for (int j = 0; j < 4; j++)
                    trow[(w0 + j) * NCH + c] = fsig(r[j]);
            } else if (c == 0) {
                #pragma unroll
                for (int j = 0; j < 4; j++)
                    trow[(w0 + j) * NCH] = (fsig(r[j]) + (float)(w0 + j)) * 8.0f;
            } else if (c == 1) {
                #pragma unroll
                for (int j = 0; j < 4; j++)
                    trow[(w0 + j) * NCH + 1] = (fsig(r[j]) + hf) * 8.0f;
            } else if (c == 2) {
                #pragma unroll
                for (int j = 0; j < 4; j++)
                    trow[(w0 + j) * NCH + 2] = fexp(r[j]) * aw;
            } else if (c == 3) {
                #pragma unroll
                for (int j = 0; j < 4; j++)
                    trow[(w0 + j) * NCH + 3] = fexp(r[j]) * ah;
            } else { // c == 4
                #pragma unroll
                for (int j = 0; j < 4; j++) {
                    float val = fsig(r[j]);
                    int w = w0 + j;
                    if (g_mask[cellbase + w]) {
                        lsum -= flg2(1.0f - val) * LN2;   // BCE t=0 branch
                        lcnt++;
                    }
                    trow[w * NCH + 4] = val;
                }
            }
        }
    }

    // block-level noobj reduction -> one private STG (no atomics)
    #pragma unroll
    for (int off = 16; off; off >>= 1) {
        lsum += __shfl_down_sync(0xffffffffu, lsum, off);
        lcnt += __shfl_down_sync(0xffffffffu, lcnt, off);
    }
    if ((tid & 31) == 0) { s_wsum[tid >> 5] = lsum; s_wcnt[tid >> 5] = lcnt; }
    __syncthreads();
    if (tid == 0) {
        float fs = 0.0f; int fc = 0;
        #pragma unroll
        for (int w = 0; w < 16; w++) { fs += s_wsum[w]; fc += s_wcnt[w]; }
        g_psum[bx] = fs;
        g_pcnt[bx] = fc;
    }

    // contiguous write: both rows back-to-back = 2210 float4
    size_t pos0 = (size_t)(b * AN + a) * HWSZ + (size_t)h0 * WW;
    float4* o = reinterpret_cast<float4*>(out + pos0 * NCH);
    const float4* ts = reinterpret_cast<const float4*>(tile);
    #pragma unroll 5
    for (int i = tid; i < 2 * VECS; i += TMAIN) o[i] = ts[i];
}

// ---------------- kernel 3: finalize (partials + obj-cell losses) ----------------
__global__ __launch_bounds__(256) void k_fin(const float* __restrict__ x,
                                             float* __restrict__ out,
                                             int nblk, int N, int out_size) {
    __shared__ int    sc[MAXN];
    __shared__ double s_dsum[8];
    __shared__ int    s_dcnt[8];
    __shared__ float  acc[6];
    __shared__ int    s_nobj;

    int tid = threadIdx.x;

    // reduce noobj partials
    double dsum = 0.0; int dcnt = 0;
    for (int i = tid; i < nblk; i += 256) { dsum += (double)g_psum[i]; dcnt += g_pcnt[i]; }
    #pragma unroll
    for (int off = 16; off; off >>= 1) {
        dsum += __shfl_down_sync(0xffffffffu, dsum, off);
        dcnt += __shfl_down_sync(0xffffffffu, dcnt, off);
    }
    if ((tid & 31) == 0) { s_dsum[tid >> 5] = dsum; s_dcnt[tid >> 5] = dcnt; }

    if (tid == 0) { acc[0]=acc[1]=acc[2]=acc[3]=acc[4]=acc[5]=0.0f; s_nobj = 0; }
    if (tid < N) sc[tid] = g_cell[tid];
    __syncthreads();

    if (tid < N) {
        // last-write-wins dedupe
        bool win = true;
        for (int m = tid + 1; m < N; m++)
            if (sc[m] == sc[tid]) { win = false; break; }
        if (win) {
            int cell = sc[tid];
            int i = cell % WW;
            int j = (cell / WW) % HH;
            int aa = (cell / HWSZ) % AN;
            int bb = cell / (AN * HWSZ);
            const float* xb2 = x + ((size_t)(bb * AN + aa) * NCH) * HWSZ
                                 + (size_t)j * WW + i;
            float z0 = xb2[0];
            float z2 = xb2[(size_t)2 * HWSZ];
            float z4 = xb2[(size_t)4 * HWSZ];
            float cx = fsig(z0);
            float dx = cx - g_tx[tid];
            float dy = cx - g_ty[tid];        // reference bug: y-loss uses cx
            float dw = z2 - g_tw[tid];
            float dh = z2 - g_th[tid];        // reference bug: h-loss uses pw
            float p4 = fmaxf(fsig(z4), 1e-12f);
            float conf = -flg2(p4) * LN2;     // t=1 at obj cell
            int lab = g_lab[tid];
            float cls = 0.0f;
            for (int c = 0; c < NC; c++) {
                float p = fmaxf(fsig(xb2[(size_t)(5 + c) * HWSZ]), 1e-12f);
                cls -= (c == lab) ? flg2(p) * LN2 : flg2(1.0f - p) * LN2;
            }
            atomicAdd(&acc[0], dx * dx);
            atomicAdd(&acc[1], dy * dy);
            atomicAdd(&acc[2], dw * dw);
            atomicAdd(&acc[3], dh * dh);
            atomicAdd(&acc[4], conf);
            atomicAdd(&acc[5], cls);
            atomicAdd(&s_nobj, 1);
        }
    }
    __syncthreads();
    if (tid == 0) {
        double nsum = 0.0; int ncnt = 0;
        #pragma unroll
        for (int w = 0; w < 8; w++) { nsum += s_dsum[w]; ncnt += s_dcnt[w]; }
        float nobj = fmaxf((float)s_nobj, 1.0f);
        float nno  = fmaxf((float)ncnt, 1.0f);
        float total = (acc[0] + acc[1] + acc[2] + acc[3]) / nobj
                    + 1.0f * (acc[4] / nobj)
                    + 0.5f * (float)(nsum / (double)nno)
                    + acc[5] / (nobj * (float)NC);
        out[out_size - 1] = total;
    }
}

// ---------------- launcher ----------------
extern "C" void kernel_launch(void* const* d_in, const int* in_sizes, int n_in,
                              void* d_out, int out_size) {
    const float* x   = (const float*)d_in[0];
    const float* tgt = (const float*)d_in[1];
    float* out = (float*)d_out;

    int B = in_sizes[0] / (AN * NCH * HWSZ);   // 16
    int N = in_sizes[1] / 6;                   // 256
    int nblk = B * AN * (HH / 2);              // 1248

    k_setup<<<1, 256>>>(tgt, N);
    k_main<<<nblk, TMAIN>>>(x, out);
    k_fin<<<1, 256>>>(x, out, nblk, N, out_size);
}

// round 5
// speedup vs baseline: 12.0052x; 2.8118x over previous
#include <cuda_runtime.h>
#include <cstdint>

// ---------------- problem constants ----------------
#define AN      3
#define NC      80
#define NCH     85          // C+5
#define HH      52
#define WW      52
#define HWSZ    (HH*WW)     // 2704
#define MAXN    256
#define ROWF4   13          // 52 floats / 4
#define VECS    (NCH*ROWF4) // 1105 float4 per (b,a,h) row
#define TILEF   (NCH*WW)    // 4420 floats per row
#define TMAIN   512
#define MAXBLK  1280
#define CELLS   (16*AN*HWSZ)

__constant__ float c_aw[AN] = {10.f, 16.f, 33.f};
__constant__ float c_ah[AN] = {13.f, 30.f, 23.f};

// ---------------- device scratch (no allocations allowed) ----------------
__device__ int    g_mask_i[CELLS];     // dedupe scratch (only touched cells used)
__device__ float  g_psum[MAXBLK];      // per-block noobj lg2 partial sums
__device__ int    g_cell[MAXN];
__device__ float  g_tx[MAXN], g_ty[MAXN], g_tw[MAXN], g_th[MAXN];
__device__ int    g_lab[MAXN];
__device__ int    g_mcell[4*MAXN];     // masked-cell candidate list
__device__ unsigned char g_mwin[4*MAXN];
__device__ unsigned char g_owin[MAXN];
__device__ int    g_mcnt;              // # unique masked cells

// ---- fast math helpers ----
#define L2E 1.4426950408889634f
#define LN2 0.6931471805599453f

__device__ __forceinline__ float fex2(float x) {
    float r; asm("ex2.approx.ftz.f32 %0, %1;" : "=f"(r) : "f"(x)); return r;
}
__device__ __forceinline__ float frcp(float x) {
    float r; asm("rcp.approx.ftz.f32 %0, %1;" : "=f"(r) : "f"(x)); return r;
}
__device__ __forceinline__ float flg2(float x) {
    float r; asm("lg2.approx.ftz.f32 %0, %1;" : "=f"(r) : "f"(x)); return r;
}
__device__ __forceinline__ float fsig(float z) { return frcp(1.0f + fex2(-L2E * z)); }
__device__ __forceinline__ float fexp(float z) { return fex2(L2E * z); }

// ---------------- kernel 1: setup (targets + dedupe; NO big mask init) ----------------
__global__ __launch_bounds__(256) void k_setup(const float* __restrict__ t, int N) {
    __shared__ int s_mcnt;
    int n = threadIdx.x;
    if (n == 0) s_mcnt = 0;

    int cells[4] = {-1, -1, -1, -1};
    int mycell = -1;

    if (n < N) {
        const float* tn = t + 6 * n;
        int   img = (int)tn[0];
        float gx = tn[1] * (float)WW;
        float gy = tn[2] * (float)HH;
        float gw = tn[3] * (float)WW;
        float gh = tn[4] * (float)HH;
        int   lab = (int)tn[5];

        float iou[AN];
        int best = 0;
        #pragma unroll
        for (int a = 0; a < AN; a++) {
            float aw = c_aw[a], ah = c_ah[a];
            float inter = fminf(aw, gw) * fminf(ah, gh);
            iou[a] = inter / (aw * ah + 1e-16f + gw * gh - inter);
        }
        if (iou[1] > iou[best]) best = 1;
        if (iou[2] > iou[best]) best = 2;

        int gi = (int)gx;
        int gj = (int)gy;
        mycell = ((img * AN + best) * HH + gj) * WW + gi;

        g_cell[n] = mycell;
        g_tx[n]   = gx - floorf(gx);
        g_ty[n]   = gy - floorf(gy);
        g_tw[n]   = logf(gw / c_aw[best] + 1e-16f);
        g_th[n]   = logf(gh / c_ah[best] + 1e-16f);
        g_lab[n]  = lab;

        cells[0] = mycell;                         // obj cell always masked
        #pragma unroll
        for (int a = 0; a < AN; a++)
            if (iou[a] > 0.5f)
                cells[a + 1] = ((img * AN + a) * HH + gj) * WW + gi;

        #pragma unroll
        for (int k = 0; k < 4; k++) {
            g_mcell[4 * n + k] = cells[k];
            if (cells[k] >= 0) g_mask_i[cells[k]] = 0;   // re-init each replay
        }
    } else {
        #pragma unroll
        for (int k = 0; k < 4; k++) g_mcell[4 * n + k] = -1;
    }
    __syncthreads();

    // unique-masked dedupe (any-winner, deterministic count & set)
    #pragma unroll
    for (int k = 0; k < 4; k++) {
        unsigned char w = 0;
        if (cells[k] >= 0 && atomicExch(&g_mask_i[cells[k]], 1) == 0) {
            w = 1; atomicAdd(&s_mcnt, 1);
        }
        g_mwin[4 * n + k] = w;
    }
    __syncthreads();

    // obj-cell last-write-wins dedupe
    if (n < N) atomicMax(&g_mask_i[mycell], 2 + n);
    __syncthreads();
    if (n < N) g_owin[n] = (g_mask_i[mycell] == 2 + n);
    if (n == 0) g_mcnt = s_mcnt;
}

// transform one float4 of channel c, grid columns w0..w0+3, into trow ([w][c] layout)
#define PROC(v, c, w0, trow, hf) do {                                         \
    float e0 = fsig((v).x), e1 = fsig((v).y), e2 = fsig((v).z), e3 = fsig((v).w); \
    if ((c) < 5) {                                                            \
        if ((c) == 0) {                                                       \
            e0 = (e0 + (float)(w0)) * 8.0f;  e1 = (e1 + (float)((w0)+1)) * 8.0f; \
            e2 = (e2 + (float)((w0)+2)) * 8.0f; e3 = (e3 + (float)((w0)+3)) * 8.0f; \
        } else if ((c) == 1) {                                                \
            e0 = (e0 + (hf)) * 8.0f; e1 = (e1 + (hf)) * 8.0f;                 \
            e2 = (e2 + (hf)) * 8.0f; e3 = (e3 + (hf)) * 8.0f;                 \
        } else if ((c) == 2) {                                                \
            e0 = fexp((v).x) * aw; e1 = fexp((v).y) * aw;                     \
            e2 = fexp((v).z) * aw; e3 = fexp((v).w) * aw;                     \
        } else if ((c) == 3) {                                                \
            e0 = fexp((v).x) * ah; e1 = fexp((v).y) * ah;                     \
            e2 = fexp((v).z) * ah; e3 = fexp((v).w) * ah;                     \
        } else {  /* c == 4: unconditional noobj BCE (lg2 units) */           \
            lsum += flg2(1.0f - e0) + flg2(1.0f - e1)                         \
                  + flg2(1.0f - e2) + flg2(1.0f - e3);                        \
        }                                                                     \
    }                                                                         \
    (trow)[(w0) * NCH + (c)]     = e0;                                        \
    (trow)[((w0)+1) * NCH + (c)] = e1;                                        \
    (trow)[((w0)+2) * NCH + (c)] = e2;                                        \
    (trow)[((w0)+3) * NCH + (c)] = e3;                                        \
} while (0)

// ---------------- kernel 2: transform + transpose, 2 rows/block, mask-free ----------------
__global__ __launch_bounds__(TMAIN) void k_main(const float* __restrict__ x,
                                                float* __restrict__ out) {
    __shared__ float tile[2 * TILEF];
    __shared__ float s_wsum[16];

    const int tid = threadIdx.x;
    const int bx = blockIdx.x;
    const int hp = bx % (HH / 2);
    const int a  = (bx / (HH / 2)) % AN;
    const int b  = bx / ((HH / 2) * AN);
    const int h0 = hp * 2;

    const float aw = c_aw[a], ah = c_ah[a];
    const float hf0 = (float)h0, hf1 = (float)(h0 + 1);
    const float* __restrict__ p0 =
        x + ((size_t)(b * AN + a) * NCH) * HWSZ + (size_t)h0 * WW;
    const float* __restrict__ p1 = p0 + WW;

    // hoisted index decomposition (3 divisions total)
    const int idxA = tid, idxB = tid + TMAIN, idxC = tid + 2 * TMAIN;
    const int cA = idxA / ROWF4, wA = (idxA - cA * ROWF4) * 4;
    const int cB = idxB / ROWF4, wB = (idxB - cB * ROWF4) * 4;
    const bool vC = (idxC < VECS);
    const int cCt = vC ? idxC / ROWF4 : 0;
    const int wC = vC ? (idxC - cCt * ROWF4) * 4 : 0;

    // 6 independent prefetched loads (MLP=6)
    float4 vA0 = *reinterpret_cast<const float4*>(p0 + (size_t)cA * HWSZ + wA);
    float4 vA1 = *reinterpret_cast<const float4*>(p1 + (size_t)cA * HWSZ + wA);
    float4 vB0 = *reinterpret_cast<const float4*>(p0 + (size_t)cB * HWSZ + wB);
    float4 vB1 = *reinterpret_cast<const float4*>(p1 + (size_t)cB * HWSZ + wB);
    float4 vC0, vC1;
    if (vC) {
        vC0 = *reinterpret_cast<const float4*>(p0 + (size_t)cCt * HWSZ + wC);
        vC1 = *reinterpret_cast<const float4*>(p1 + (size_t)cCt * HWSZ + wC);
    }

    float* trow0 = tile;
    float* trow1 = tile + TILEF;
    float lsum = 0.0f;

    PROC(vA0, cA, wA, trow0, hf0);
    PROC(vA1, cA, wA, trow1, hf1);
    PROC(vB0, cB, wB, trow0, hf0);
    PROC(vB1, cB, wB, trow1, hf1);
    if (vC) {
        PROC(vC0, cCt, wC, trow0, hf0);
        PROC(vC1, cCt, wC, trow1, hf1);
    }

    // block reduce of lg2 partial (no count needed; count is analytic)
    #pragma unroll
    for (int off = 16; off; off >>= 1)
        lsum += __shfl_down_sync(0xffffffffu, lsum, off);
    if ((tid & 31) == 0) s_wsum[tid >> 5] = lsum;
    __syncthreads();
    if (tid == 0) {
        float fs = 0.0f;
        #pragma unroll
        for (int w = 0; w < 16; w++) fs += s_wsum[w];
        g_psum[bx] = fs;
    }

    // contiguous copy-out: 2210 float4
    size_t pos0 = (size_t)(b * AN + a) * HWSZ + (size_t)h0 * WW;
    float4* o = reinterpret_cast<float4*>(out + pos0 * NCH);
    const float4* ts = reinterpret_cast<const float4*>(tile);
    o[tid]            = ts[tid];
    o[tid + 512]      = ts[tid + 512];
    o[tid + 1024]     = ts[tid + 1024];
    o[tid + 1536]     = ts[tid + 1536];
    if (tid < 2 * VECS - 2048) o[tid + 2048] = ts[tid + 2048];
}

// ---------------- kernel 3: finalize ----------------
__global__ __launch_bounds__(256) void k_fin(const float* __restrict__ x,
                                             float* __restrict__ out,
                                             int nblk, int N, int ncells,
                                             int out_size) {
    __shared__ double s_d[8];
    __shared__ float  acc[6];
    __shared__ int    s_nobj;

    int tid = threadIdx.x;
    if (tid == 0) { acc[0]=acc[1]=acc[2]=acc[3]=acc[4]=acc[5]=0.0f; s_nobj = 0; }
    __syncthreads();

    // 1. reduce per-block noobj partials (lg2 units)
    double dsum = 0.0;
    for (int i = tid; i < nblk; i += 256) dsum += (double)g_psum[i];

    // 2. subtract masked cells' contributions (identical fsig/flg2 formula)
    float fsub = 0.0f;
    #pragma unroll
    for (int k = 0; k < 4; k++) {
        int e = tid + k * 256;
        if (g_mwin[e]) {
            int cell = g_mcell[e];
            int i  = cell % WW;
            int j  = (cell / WW) % HH;
            int aa = (cell / HWSZ) % AN;
            int bb = cell / (AN * HWSZ);
            float z4 = x[((size_t)((bb * AN + aa) * NCH) + 4) * HWSZ
                         + (size_t)j * WW + i];
            fsub += flg2(1.0f - fsig(z4));
        }
    }
    dsum -= (double)fsub;
    #pragma unroll
    for (int off = 16; off; off >>= 1)
        dsum += __shfl_down_sync(0xffffffffu, dsum, off);
    if ((tid & 31) == 0) s_d[tid >> 5] = dsum;

    // 3. obj-cell losses
    if (tid < N && g_owin[tid]) {
        int cell = g_cell[tid];
        int i  = cell % WW;
        int j  = (cell / WW) % HH;
        int aa = (cell / HWSZ) % AN;
        int bb = cell / (AN * HWSZ);
        const float* xb2 = x + ((size_t)(bb * AN + aa) * NCH) * HWSZ
                             + (size_t)j * WW + i;
        float z0 = xb2[0];
        float z2 = xb2[(size_t)2 * HWSZ];
        float z4 = xb2[(size_t)4 * HWSZ];
        float cx = fsig(z0);
        float dx = cx - g_tx[tid];
        float dy = cx - g_ty[tid];        // reference bug: y-loss uses cx
        float dw = z2 - g_tw[tid];
        float dh = z2 - g_th[tid];        // reference bug: h-loss uses pw
        float p4 = fmaxf(fsig(z4), 1e-12f);
        float conf = -flg2(p4) * LN2;     // t=1 at obj cell
        int lab = g_lab[tid];
        float cls = 0.0f;
        for (int c = 0; c < NC; c++) {
            float p = fmaxf(fsig(xb2[(size_t)(5 + c) * HWSZ]), 1e-12f);
            cls -= (c == lab) ? flg2(p) * LN2 : flg2(1.0f - p) * LN2;
        }
        atomicAdd(&acc[0], dx * dx);
        atomicAdd(&acc[1], dy * dy);
        atomicAdd(&acc[2], dw * dw);
        atomicAdd(&acc[3], dh * dh);
        atomicAdd(&acc[4], conf);
        atomicAdd(&acc[5], cls);
        atomicAdd(&s_nobj, 1);
    }
    __syncthreads();
    if (tid == 0) {
        double net = 0.0;
        #pragma unroll
        for (int w = 0; w < 8; w++) net += s_d[w];
        float nobj = fmaxf((float)s_nobj, 1.0f);
        float nno  = fmaxf((float)(ncells - g_mcnt), 1.0f);
        float noobj_bce = (float)(-(double)LN2 * net / (double)nno);
        float total = (acc[0] + acc[1] + acc[2] + acc[3]) / nobj
                    + 1.0f * (acc[4] / nobj)
                    + 0.5f * noobj_bce
                    + acc[5] / (nobj * (float)NC);
        out[out_size - 1] = total;
    }
}

// ---------------- launcher ----------------
extern "C" void kernel_launch(void* const* d_in, const int* in_sizes, int n_in,
                              void* d_out, int out_size) {
    const float* x   = (const float*)d_in[0];
    const float* tgt = (const float*)d_in[1];
    float* out = (float*)d_out;

    int B = in_sizes[0] / (AN * NCH * HWSZ);   // 16
    int N = in_sizes[1] / 6;                   // 256
    int nblk = B * AN * (HH / 2);              // 1248
    int ncells = B * AN * HWSZ;                // 129792

    k_setup<<<1, 256>>>(tgt, N);
    k_main<<<nblk, TMAIN>>>(x, out);
    k_fin<<<1, 256>>>(x, out, nblk, N, ncells, out_size);
}

// round 6
// speedup vs baseline: 12.3760x; 1.0309x over previous
#include <cuda_runtime.h>
#include <cstdint>

// ---------------- problem constants ----------------
#define AN      3
#define NC      80
#define NCH     85          // C+5
#define HH      52
#define WW      52
#define HWSZ    (HH*WW)     // 2704
#define MAXN    256
#define ROWF4   13          // 52 floats / 4
#define VECS    (NCH*ROWF4) // 1105 float4 per (b,a,h) row
#define TILEF   (NCH*WW)    // 4420 floats per row
#define TMAIN   512
#define MAXBLK  1280
#define CELLS   (16*AN*HWSZ)

__constant__ float c_aw[AN] = {10.f, 16.f, 33.f};
__constant__ float c_ah[AN] = {13.f, 30.f, 23.f};

// ---------------- device scratch (no allocations allowed) ----------------
__device__ int    g_mask_i[CELLS];     // dedupe scratch (only touched cells used)
__device__ float  g_psum[MAXBLK];      // per-block noobj lg2 partial sums
__device__ int    g_cell[MAXN];
__device__ float  g_tx[MAXN], g_ty[MAXN], g_tw[MAXN], g_th[MAXN];
__device__ int    g_lab[MAXN];
__device__ int    g_mcell[4*MAXN];     // masked-cell candidate list
__device__ unsigned char g_mwin[4*MAXN];
__device__ unsigned char g_owin[MAXN];
__device__ int    g_mcnt;              // # unique masked cells
__device__ unsigned int g_done;        // zero at load; winner resets each replay

// ---- fast math helpers ----
#define L2E 1.4426950408889634f
#define LN2 0.6931471805599453f

__device__ __forceinline__ float fex2(float x) {
    float r; asm("ex2.approx.ftz.f32 %0, %1;" : "=f"(r) : "f"(x)); return r;
}
__device__ __forceinline__ float frcp(float x) {
    float r; asm("rcp.approx.ftz.f32 %0, %1;" : "=f"(r) : "f"(x)); return r;
}
__device__ __forceinline__ float flg2(float x) {
    float r; asm("lg2.approx.ftz.f32 %0, %1;" : "=f"(r) : "f"(x)); return r;
}
__device__ __forceinline__ float fsig(float z) { return frcp(1.0f + fex2(-L2E * z)); }
__device__ __forceinline__ float fexp(float z) { return fex2(L2E * z); }

// transform one float4 of channel c, grid columns w0..w0+3, into trow ([w][c] layout)
#define PROC(v, c, w0, trow, hf) do {                                         \
    float e0 = fsig((v).x), e1 = fsig((v).y), e2 = fsig((v).z), e3 = fsig((v).w); \
    if ((c) < 5) {                                                            \
        if ((c) == 0) {                                                       \
            e0 = (e0 + (float)(w0)) * 8.0f;  e1 = (e1 + (float)((w0)+1)) * 8.0f; \
            e2 = (e2 + (float)((w0)+2)) * 8.0f; e3 = (e3 + (float)((w0)+3)) * 8.0f; \
        } else if ((c) == 1) {                                                \
            e0 = (e0 + (hf)) * 8.0f; e1 = (e1 + (hf)) * 8.0f;                 \
            e2 = (e2 + (hf)) * 8.0f; e3 = (e3 + (hf)) * 8.0f;                 \
        } else if ((c) == 2) {                                                \
            e0 = fexp((v).x) * aw; e1 = fexp((v).y) * aw;                     \
            e2 = fexp((v).z) * aw; e3 = fexp((v).w) * aw;                     \
        } else if ((c) == 3) {                                                \
            e0 = fexp((v).x) * ah; e1 = fexp((v).y) * ah;                     \
            e2 = fexp((v).z) * ah; e3 = fexp((v).w) * ah;                     \
        } else {  /* c == 4: unconditional noobj BCE (lg2 units) */           \
            lsum += flg2(1.0f - e0) + flg2(1.0f - e1)                         \
                  + flg2(1.0f - e2) + flg2(1.0f - e3);                        \
        }                                                                     \
    }                                                                         \
    (trow)[(w0) * NCH + (c)]     = e0;                                        \
    (trow)[((w0)+1) * NCH + (c)] = e1;                                        \
    (trow)[((w0)+2) * NCH + (c)] = e2;                                        \
    (trow)[((w0)+3) * NCH + (c)] = e3;                                        \
} while (0)

// ================= single fused kernel =================
__global__ __launch_bounds__(TMAIN) void k_all(const float* __restrict__ x,
                                               const float* __restrict__ t,
                                               float* __restrict__ out,
                                               int N, int ncells, int out_size) {
    __shared__ float tile[2 * TILEF];
    __shared__ float s_wsum[16];
    __shared__ int   s_misc;

    const int tid = threadIdx.x;
    const int bx0 = blockIdx.x;

    if (bx0 == 0) {
        // -------- setup (block 0; hidden under the transform blocks) --------
        const int n = tid;
        if (n == 0) s_misc = 0;

        int cells[4] = {-1, -1, -1, -1};
        int mycell = -1;

        if (n < N) {
            const float* tn = t + 6 * n;
            int   img = (int)tn[0];
            float gx = tn[1] * (float)WW;
            float gy = tn[2] * (float)HH;
            float gw = tn[3] * (float)WW;
            float gh = tn[4] * (float)HH;
            int   lab = (int)tn[5];

            float iou[AN];
            int best = 0;
            #pragma unroll
            for (int a = 0; a < AN; a++) {
                float aw2 = c_aw[a], ah2 = c_ah[a];
                float inter = fminf(aw2, gw) * fminf(ah2, gh);
                iou[a] = inter / (aw2 * ah2 + 1e-16f + gw * gh - inter);
            }
            if (iou[1] > iou[best]) best = 1;
            if (iou[2] > iou[best]) best = 2;

            int gi = (int)gx;
            int gj = (int)gy;
            mycell = ((img * AN + best) * HH + gj) * WW + gi;

            g_cell[n] = mycell;
            g_tx[n]   = gx - floorf(gx);
            g_ty[n]   = gy - floorf(gy);
            g_tw[n]   = logf(gw / c_aw[best] + 1e-16f);
            g_th[n]   = logf(gh / c_ah[best] + 1e-16f);
            g_lab[n]  = lab;

            cells[0] = mycell;
            #pragma unroll
            for (int a = 0; a < AN; a++)
                if (iou[a] > 0.5f)
                    cells[a + 1] = ((img * AN + a) * HH + gj) * WW + gi;

            #pragma unroll
            for (int k = 0; k < 4; k++) {
                g_mcell[4 * n + k] = cells[k];
                if (cells[k] >= 0) g_mask_i[cells[k]] = 0;   // re-init each replay
            }
        } else if (n < MAXN) {
            #pragma unroll
            for (int k = 0; k < 4; k++) g_mcell[4 * n + k] = -1;
        }
        __syncthreads();

        if (n < MAXN) {
            #pragma unroll
            for (int k = 0; k < 4; k++) {
                unsigned char w = 0;
                if (cells[k] >= 0 && atomicExch(&g_mask_i[cells[k]], 1) == 0) {
                    w = 1; atomicAdd(&s_misc, 1);
                }
                g_mwin[4 * n + k] = w;
            }
        }
        __syncthreads();

        if (n < N) atomicMax(&g_mask_i[mycell], 2 + n);
        __syncthreads();
        if (n < N) g_owin[n] = (g_mask_i[mycell] == 2 + n);
        if (n == 0) g_mcnt = s_misc;
    } else {
        // -------- transform: 2 rows per block --------
        const int bx = bx0 - 1;
        const int hp = bx % (HH / 2);
        const int a  = (bx / (HH / 2)) % AN;
        const int b  = bx / ((HH / 2) * AN);
        const int h0 = hp * 2;

        const float aw = c_aw[a], ah = c_ah[a];
        const float hf0 = (float)h0, hf1 = (float)(h0 + 1);
        const float* __restrict__ p0 =
            x + ((size_t)(b * AN + a) * NCH) * HWSZ + (size_t)h0 * WW;
        const float* __restrict__ p1 = p0 + WW;

        const int idxA = tid, idxB = tid + TMAIN, idxC = tid + 2 * TMAIN;
        const int cA = idxA / ROWF4, wA = (idxA - cA * ROWF4) * 4;
        const int cB = idxB / ROWF4, wB = (idxB - cB * ROWF4) * 4;
        const bool vC = (idxC < VECS);
        const int cCt = vC ? idxC / ROWF4 : 0;
        const int wC = vC ? (idxC - cCt * ROWF4) * 4 : 0;

        float4 vA0 = *reinterpret_cast<const float4*>(p0 + (size_t)cA * HWSZ + wA);
        float4 vA1 = *reinterpret_cast<const float4*>(p1 + (size_t)cA * HWSZ + wA);
        float4 vB0 = *reinterpret_cast<const float4*>(p0 + (size_t)cB * HWSZ + wB);
        float4 vB1 = *reinterpret_cast<const float4*>(p1 + (size_t)cB * HWSZ + wB);
        float4 vC0, vC1;
        if (vC) {
            vC0 = *reinterpret_cast<const float4*>(p0 + (size_t)cCt * HWSZ + wC);
            vC1 = *reinterpret_cast<const float4*>(p1 + (size_t)cCt * HWSZ + wC);
        }

        float* trow0 = tile;
        float* trow1 = tile + TILEF;
        float lsum = 0.0f;

        PROC(vA0, cA, wA, trow0, hf0);
        PROC(vA1, cA, wA, trow1, hf1);
        PROC(vB0, cB, wB, trow0, hf0);
        PROC(vB1, cB, wB, trow1, hf1);
        if (vC) {
            PROC(vC0, cCt, wC, trow0, hf0);
            PROC(vC1, cCt, wC, trow1, hf1);
        }

        #pragma unroll
        for (int off = 16; off; off >>= 1)
            lsum += __shfl_down_sync(0xffffffffu, lsum, off);
        if ((tid & 31) == 0) s_wsum[tid >> 5] = lsum;
        __syncthreads();
        if (tid == 0) {
            float fs = 0.0f;
            #pragma unroll
            for (int w = 0; w < 16; w++) fs += s_wsum[w];
            g_psum[bx] = fs;
        }

        size_t pos0 = (size_t)(b * AN + a) * HWSZ + (size_t)h0 * WW;
        float4* o = reinterpret_cast<float4*>(out + pos0 * NCH);
        const float4* ts = reinterpret_cast<const float4*>(tile);
        o[tid]            = ts[tid];
        o[tid + 512]      = ts[tid + 512];
        o[tid + 1024]     = ts[tid + 1024];
        o[tid + 1536]     = ts[tid + 1536];
        if (tid < 2 * VECS - 2048) o[tid + 2048] = ts[tid + 2048];
    }

    // -------- last-block election --------
    __threadfence();
    __syncthreads();
    if (tid == 0)
        s_misc = (atomicAdd(&g_done, 1u) == (unsigned)(gridDim.x - 1));
    __syncthreads();
    if (!s_misc) return;

    // -------- finalize (winning block only) --------
    {
        __shared__ double s_d[16];
        __shared__ float  acc[6];
        __shared__ int    s_nobj;
        const int nblk = (int)gridDim.x - 1;

        if (tid == 0) { acc[0]=acc[1]=acc[2]=acc[3]=acc[4]=acc[5]=0.0f; s_nobj = 0; }
        __syncthreads();

        double dsum = 0.0;
        for (int i = tid; i < nblk; i += TMAIN) dsum += (double)g_psum[i];

        float fsub = 0.0f;
        #pragma unroll
        for (int k = 0; k < 2; k++) {
            int e = tid + k * TMAIN;
            if (e < 4 * MAXN && g_mwin[e]) {
                int cell = g_mcell[e];
                int i  = cell % WW;
                int j  = (cell / WW) % HH;
                int aa = (cell / HWSZ) % AN;
                int bb = cell / (AN * HWSZ);
                float z4 = x[((size_t)((bb * AN + aa) * NCH) + 4) * HWSZ
                             + (size_t)j * WW + i];
                fsub += flg2(1.0f - fsig(z4));
            }
        }
        dsum -= (double)fsub;
        #pragma unroll
        for (int off = 16; off; off >>= 1)
            dsum += __shfl_down_sync(0xffffffffu, dsum, off);
        if ((tid & 31) == 0) s_d[tid >> 5] = dsum;

        if (tid < N && g_owin[tid]) {
            int cell = g_cell[tid];
            int i  = cell % WW;
            int j  = (cell / WW) % HH;
            int aa = (cell / HWSZ) % AN;
            int bb = cell / (AN * HWSZ);
            const float* xb2 = x + ((size_t)(bb * AN + aa) * NCH) * HWSZ
                                 + (size_t)j * WW + i;
            float z0 = xb2[0];
            float z2 = xb2[(size_t)2 * HWSZ];
            float z4 = xb2[(size_t)4 * HWSZ];
            float cx = fsig(z0);
            float dx = cx - g_tx[tid];
            float dy = cx - g_ty[tid];        // reference bug: y-loss uses cx
            float dw = z2 - g_tw[tid];
            float dh = z2 - g_th[tid];        // reference bug: h-loss uses pw
            float p4 = fmaxf(fsig(z4), 1e-12f);
            float conf = -flg2(p4) * LN2;     // t=1 at obj cell
            int lab = g_lab[tid];
            float cls = 0.0f;
            #pragma unroll 4
            for (int c = 0; c < NC; c++) {
                float p = fmaxf(fsig(xb2[(size_t)(5 + c) * HWSZ]), 1e-12f);
                cls -= (c == lab) ? flg2(p) * LN2 : flg2(1.0f - p) * LN2;
            }
            atomicAdd(&acc[0], dx * dx);
            atomicAdd(&acc[1], dy * dy);
            atomicAdd(&acc[2], dw * dw);
            atomicAdd(&acc[3], dh * dh);
            atomicAdd(&acc[4], conf);
            atomicAdd(&acc[5], cls);
            atomicAdd(&s_nobj, 1);
        }
        __syncthreads();
        if (tid == 0) {
            double net = 0.0;
            #pragma unroll
            for (int w = 0; w < 16; w++) net += s_d[w];
            float nobj = fmaxf((float)s_nobj, 1.0f);
            float nno  = fmaxf((float)(ncells - g_mcnt), 1.0f);
            float noobj_bce = (float)(-(double)LN2 * net / (double)nno);
            float total = (acc[0] + acc[1] + acc[2] + acc[3]) / nobj
                        + 1.0f * (acc[4] / nobj)
                        + 0.5f * noobj_bce
                        + acc[5] / (nobj * (float)NC);
            out[out_size - 1] = total;
            g_done = 0u;                      // reset for next replay
        }
    }
}

// ---------------- launcher ----------------
extern "C" void kernel_launch(void* const* d_in, const int* in_sizes, int n_in,
                              void* d_out, int out_size) {
    const float* x   = (const float*)d_in[0];
    const float* tgt = (const float*)d_in[1];
    float* out = (float*)d_out;

    int B = in_sizes[0] / (AN * NCH * HWSZ);   // 16
    int N = in_sizes[1] / 6;                   // 256
    int nblk = B * AN * (HH / 2);              // 1248
    int ncells = B * AN * HWSZ;                // 129792

    k_all<<<nblk + 1, TMAIN>>>(x, tgt, out, N, ncells, out_size);
}